// round 2
// baseline (speedup 1.0000x reference)
#include <cuda_runtime.h>
#include <cstdint>

#define EPSV  1e-5f
#define SLOPE 0.01f

// ---------------- scratch (device globals; no allocation allowed) ----------
__device__ float g_h1[32u * 256u * 1024u];   // after layer1
__device__ float g_h2[32u * 512u * 512u];    // after layer2
__device__ float g_h3[32u * 512u * 256u];    // after layer3
__device__ float g_h4[32u * 128u * 256u];    // after layer4
__device__ float g_fnorm[8192];
__device__ float g_enorm[4096];
__device__ float g_pval[8192 * 32];
__device__ int   g_pidx[8192 * 32];
// fallbacks if the harness output layout differs from codes||dist
__device__ float g_dist_scratch[8192ull * 4096ull];
__device__ float g_codes_scratch[8192];

// ---------------------------------------------------------------------------
// Conv1d(k=3, pad=1) + BatchNorm(eval) + LeakyReLU as implicit GEMM.
//   C[o, n] = sum_{kk} W[o, kk] * X[kk, n],  kk = i*3+k,  n = b*LOUT + l
//   X[kk, n] = in[b, i, STRIDE*l + k - 1]  (zero padded)
// Block tile 128x128, K tile 16, 256 threads, 8x8 per-thread micro-tile.
// ---------------------------------------------------------------------------
template <int IC, int OC, int LIN, int LOUT, int STRIDE>
__global__ __launch_bounds__(256)
void conv_bn_lrelu(const float* __restrict__ in,   // [B, IC, LIN]
                   const float* __restrict__ w,    // [OC, IC*3]
                   const float* __restrict__ bias, // [OC]
                   const float* __restrict__ gg,
                   const float* __restrict__ be,
                   const float* __restrict__ mm,
                   const float* __restrict__ vv,
                   float* __restrict__ out)        // [B, OC, LOUT]
{
    constexpr int KD = IC * 3;
    const int n0 = blockIdx.x * 128;        // LOUT multiple of 128 => tile stays
    const int b  = n0 / LOUT;               // inside one batch element
    const int l0 = n0 % LOUT;
    const int o0 = blockIdx.y * 128;

    __shared__ float As[16][132];           // [k][o] transposed, padded
    __shared__ float Bs[16][132];           // [k][n], padded

    const int tid = threadIdx.x;
    const int tx = tid & 15;                // n micro-tile
    const int ty = tid >> 4;                // o micro-tile

    float acc[8][8];
#pragma unroll
    for (int i = 0; i < 8; i++)
#pragma unroll
        for (int j = 0; j < 8; j++) acc[i][j] = 0.f;

    const float* __restrict__ inb = in + (size_t)b * IC * LIN;

    for (int k0 = 0; k0 < KD; k0 += 16) {
        // --- load A tile (weights) 128(o) x 16(k) ---
#pragma unroll
        for (int j = 0; j < 8; j++) {
            int idx = tid + 256 * j;
            int ol  = idx >> 4;
            int kl  = idx & 15;
            As[kl][ol] = w[(size_t)(o0 + ol) * KD + (k0 + kl)];
        }
        // --- load B tile (im2col gather) 16(k) x 128(n) ---
#pragma unroll
        for (int j = 0; j < 8; j++) {
            int idx = tid + 256 * j;
            int kl  = idx >> 7;
            int nl  = idx & 127;
            int kk  = k0 + kl;
            int ci  = kk / 3;
            int kw  = kk - ci * 3;
            int pos = STRIDE * (l0 + nl) + kw - 1;
            float v = 0.f;
            if (pos >= 0 && pos < LIN) v = inb[(size_t)ci * LIN + pos];
            Bs[kl][nl] = v;
        }
        __syncthreads();

#pragma unroll
        for (int k = 0; k < 16; k++) {
            float a[8], bb[8];
            *(float4*)&a[0]  = *(const float4*)&As[k][ty * 8];
            *(float4*)&a[4]  = *(const float4*)&As[k][ty * 8 + 4];
            *(float4*)&bb[0] = *(const float4*)&Bs[k][tx * 8];
            *(float4*)&bb[4] = *(const float4*)&Bs[k][tx * 8 + 4];
#pragma unroll
            for (int i = 0; i < 8; i++)
#pragma unroll
                for (int j = 0; j < 8; j++)
                    acc[i][j] = fmaf(a[i], bb[j], acc[i][j]);
        }
        __syncthreads();
    }

    // --- fused BN + LeakyReLU epilogue ---
#pragma unroll
    for (int i = 0; i < 8; i++) {
        int o = o0 + ty * 8 + i;
        float alpha = gg[o] * rsqrtf(vv[o] + EPSV);
        float beta  = (bias[o] - mm[o]) * alpha + be[o];
        float* op = out + (size_t)b * OC * LOUT + (size_t)o * LOUT + l0 + tx * 8;
        float4 r0, r1;
#pragma unroll
        for (int j = 0; j < 8; j++) {
            float t = acc[i][j] * alpha + beta;
            t = (t >= 0.f) ? t : SLOPE * t;
            if (j < 4) ((float*)&r0)[j] = t; else ((float*)&r1)[j - 4] = t;
        }
        *(float4*)op       = r0;
        *(float4*)(op + 4) = r1;
    }
}

// ---------------------------------------------------------------------------
// precompute ||emb_k||^2 (one thread per code)
// ---------------------------------------------------------------------------
__global__ void enorm_kernel(const float* __restrict__ emb)
{
    int k = blockIdx.x * 256 + threadIdx.x;     // 4096 total
    if (k >= 4096) return;
    const float* e = emb + (size_t)k * 128;
    float s = 0.f;
#pragma unroll 8
    for (int d = 0; d < 128; d++) s = fmaf(e[d], e[d], s);
    g_enorm[k] = s;
}

// precompute ||flat_n||^2, flat[n, d] = h4[b, d, l], n = b*256 + l
__global__ void fnorm_kernel()
{
    int n = blockIdx.x * 256 + threadIdx.x;     // 8192 total
    int b = n >> 8, l = n & 255;
    float s = 0.f;
#pragma unroll 8
    for (int d = 0; d < 128; d++) {
        float x = g_h4[((size_t)b * 128 + d) * 256 + l];
        s = fmaf(x, x, s);
    }
    g_fnorm[n] = s;
}

// ---------------------------------------------------------------------------
// VQ distance GEMM: dist[r, c] = fnorm[r] + enorm[c] - 2 * flat[r,:].emb[c,:]
// M=8192 rows, N=4096 codes, K=128. Fused per-block partial argmin.
// ---------------------------------------------------------------------------
__global__ __launch_bounds__(256)
void vq_dist(const float* __restrict__ emb, float* __restrict__ dist_out)
{
    const int c0 = blockIdx.x * 128;   // code tile (32 tiles)
    const int r0 = blockIdx.y * 128;   // row  tile (64 tiles)

    __shared__ float As[16][132];      // [d][r]
    __shared__ float Bs[16][132];      // [d][c]
    __shared__ float s_val[128 * 16];
    __shared__ int   s_idx[128 * 16];

    const int tid = threadIdx.x;
    const int tx = tid & 15;           // c micro-tile
    const int ty = tid >> 4;           // r micro-tile

    float acc[8][8];
#pragma unroll
    for (int i = 0; i < 8; i++)
#pragma unroll
        for (int j = 0; j < 8; j++) acc[i][j] = 0.f;

    for (int k0 = 0; k0 < 128; k0 += 16) {
        // A[r, d] = h4[b, d, l]
#pragma unroll
        for (int j = 0; j < 8; j++) {
            int idx = tid + 256 * j;
            int rl  = idx >> 4;
            int kl  = idx & 15;
            int r   = r0 + rl;
            int b   = r >> 8, l = r & 255;
            As[kl][rl] = g_h4[((size_t)b * 128 + (k0 + kl)) * 256 + l];
        }
        // B[d, c] = emb[c*128 + d]
#pragma unroll
        for (int j = 0; j < 8; j++) {
            int idx = tid + 256 * j;
            int cl  = idx >> 4;
            int kl  = idx & 15;
            Bs[kl][cl] = emb[(size_t)(c0 + cl) * 128 + (k0 + kl)];
        }
        __syncthreads();

#pragma unroll
        for (int k = 0; k < 16; k++) {
            float a[8], bb[8];
            *(float4*)&a[0]  = *(const float4*)&As[k][ty * 8];
            *(float4*)&a[4]  = *(const float4*)&As[k][ty * 8 + 4];
            *(float4*)&bb[0] = *(const float4*)&Bs[k][tx * 8];
            *(float4*)&bb[4] = *(const float4*)&Bs[k][tx * 8 + 4];
#pragma unroll
            for (int i = 0; i < 8; i++)
#pragma unroll
                for (int j = 0; j < 8; j++)
                    acc[i][j] = fmaf(a[i], bb[j], acc[i][j]);
        }
        __syncthreads();
    }

    // epilogue: dist values + per-thread argmin over its 8 columns
#pragma unroll
    for (int i = 0; i < 8; i++) {
        int r = r0 + ty * 8 + i;
        float fn = g_fnorm[r];
        float bv = 3.0e38f;
        int   bi = c0;
        float* dp = dist_out + (size_t)r * 4096 + c0 + tx * 8;
        float4 o0v, o1v;
#pragma unroll
        for (int j = 0; j < 8; j++) {
            int   c  = c0 + tx * 8 + j;
            float dv = fn + g_enorm[c] - 2.f * acc[i][j];
            if (j < 4) ((float*)&o0v)[j] = dv; else ((float*)&o1v)[j - 4] = dv;
            if (dv < bv) { bv = dv; bi = c; }
        }
        *(float4*)dp       = o0v;
        *(float4*)(dp + 4) = o1v;
        s_val[(ty * 8 + i) * 16 + tx] = bv;
        s_idx[(ty * 8 + i) * 16 + tx] = bi;
    }
    __syncthreads();

    // per-row reduce over the 16 tx lanes (ascending -> lowest index on ties)
    if (tid < 128) {
        float bv = s_val[tid * 16];
        int   bi = s_idx[tid * 16];
#pragma unroll
        for (int t = 1; t < 16; t++) {
            float v = s_val[tid * 16 + t];
            if (v < bv) { bv = v; bi = s_idx[tid * 16 + t]; }
        }
        g_pval[(size_t)(r0 + tid) * 32 + blockIdx.x] = bv;
        g_pidx[(size_t)(r0 + tid) * 32 + blockIdx.x] = bi;
    }
}

// final argmin reduce across the 32 column tiles; codes written as float
__global__ void vq_reduce(float* __restrict__ codes_out)
{
    int n = blockIdx.x * 256 + threadIdx.x;   // 8192 total
    float bv = g_pval[(size_t)n * 32];
    int   bi = g_pidx[(size_t)n * 32];
#pragma unroll
    for (int t = 1; t < 32; t++) {
        float v = g_pval[(size_t)n * 32 + t];
        if (v < bv) { bv = v; bi = g_pidx[(size_t)n * 32 + t]; }
    }
    codes_out[n] = (float)bi;
}

// ---------------------------------------------------------------------------
extern "C" void kernel_launch(void* const* d_in, const int* in_sizes, int n_in,
                              void* d_out, int out_size)
{
    const float* x   = (const float*)d_in[0];
    const float* w1  = (const float*)d_in[1];
    const float* b1  = (const float*)d_in[2];
    const float* w2  = (const float*)d_in[3];
    const float* b2  = (const float*)d_in[4];
    const float* w3  = (const float*)d_in[5];
    const float* b3  = (const float*)d_in[6];
    const float* w4  = (const float*)d_in[7];
    const float* b4  = (const float*)d_in[8];
    const float* g1  = (const float*)d_in[9];
    const float* be1 = (const float*)d_in[10];
    const float* m1  = (const float*)d_in[11];
    const float* v1  = (const float*)d_in[12];
    const float* g2  = (const float*)d_in[13];
    const float* be2 = (const float*)d_in[14];
    const float* m2  = (const float*)d_in[15];
    const float* v2  = (const float*)d_in[16];
    const float* g3  = (const float*)d_in[17];
    const float* be3 = (const float*)d_in[18];
    const float* m3  = (const float*)d_in[19];
    const float* v3  = (const float*)d_in[20];
    const float* g4  = (const float*)d_in[21];
    const float* be4 = (const float*)d_in[22];
    const float* m4  = (const float*)d_in[23];
    const float* v4  = (const float*)d_in[24];
    const float* emb = (const float*)d_in[25];

    void *p_h1, *p_h2, *p_h3, *p_h4, *p_dist_scr, *p_codes_scr;
    cudaGetSymbolAddress(&p_h1, g_h1);
    cudaGetSymbolAddress(&p_h2, g_h2);
    cudaGetSymbolAddress(&p_h3, g_h3);
    cudaGetSymbolAddress(&p_h4, g_h4);
    cudaGetSymbolAddress(&p_dist_scr, g_dist_scratch);
    cudaGetSymbolAddress(&p_codes_scr, g_codes_scratch);

    float* h1 = (float*)p_h1;
    float* h2 = (float*)p_h2;
    float* h3 = (float*)p_h3;
    float* h4 = (float*)p_h4;

    // Output layout: reference returns (codes, dist). Default: codes||dist.
    float* out = (float*)d_out;
    float* codes_ptr;
    float* dist_ptr;
    const long long FULL = 8192LL + 8192LL * 4096LL;
    if ((long long)out_size >= FULL) {
        codes_ptr = out;
        dist_ptr  = out + 8192;
    } else if ((long long)out_size == 8192LL * 4096LL) {
        codes_ptr = (float*)p_codes_scr;
        dist_ptr  = out;
    } else {
        codes_ptr = out;
        dist_ptr  = (float*)p_dist_scr;
    }

    // Layer 1: 256 -> 256, L 2048 -> 1024, stride 2
    conv_bn_lrelu<256, 256, 2048, 1024, 2>
        <<<dim3(256, 2), 256>>>(x, w1, b1, g1, be1, m1, v1, h1);
    // Layer 2: 256 -> 512, L 1024 -> 512, stride 2
    conv_bn_lrelu<256, 512, 1024, 512, 2>
        <<<dim3(128, 4), 256>>>(h1, w2, b2, g2, be2, m2, v2, h2);
    // Layer 3: 512 -> 512, L 512 -> 256, stride 2
    conv_bn_lrelu<512, 512, 512, 256, 2>
        <<<dim3(64, 4), 256>>>(h2, w3, b3, g3, be3, m3, v3, h3);
    // Layer 4: 512 -> 128, L 256 -> 256, stride 1
    conv_bn_lrelu<512, 128, 256, 256, 1>
        <<<dim3(64, 1), 256>>>(h3, w4, b4, g4, be4, m4, v4, h4);

    enorm_kernel<<<16, 256>>>(emb);
    fnorm_kernel<<<32, 256>>>();

    vq_dist<<<dim3(32, 64), 256>>>(emb, dist_ptr);
    vq_reduce<<<32, 256>>>(codes_ptr);
}